// round 6
// baseline (speedup 1.0000x reference)
#include <cuda_runtime.h>
#include <cuda_bf16.h>
#include <cstdint>

// ---------------------------------------------------------------------------
// Problem constants
// ---------------------------------------------------------------------------
#define LAYERS 4
#define HDIM   512
#define NHEAD  8
#define DHQK   32
#define DHV    64
#define QKDIM  (NHEAD * DHQK)   // 256
#define VDIM   (NHEAD * DHV)    // 512
#define FDIM   1408
#define NTOK   2048              // B*P = 8*256
#define CAPV   15.0f
#define EPSV   1e-6f

// ---------------------------------------------------------------------------
// Device scratch (static: no allocation allowed)
// ---------------------------------------------------------------------------
__device__ float g_x   [NTOK * HDIM];
__device__ float g_xn  [NTOK * HDIM];
__device__ float g_q   [NTOK * QKDIM];
__device__ float g_k   [NTOK * QKDIM];
__device__ float g_v   [NTOK * VDIM];
__device__ float g_og  [NTOK * VDIM];
__device__ float g_if  [NTOK * 64];
__device__ float g_hv  [NTOK * VDIM];
__device__ float g_gate[NTOK * FDIM];
__device__ float g_up  [NTOK * FDIM];
__device__ float g_wif [LAYERS * HDIM * 64];   // packed [Wi | Wf | 0...] per layer

// ---------------------------------------------------------------------------
// Helpers
// ---------------------------------------------------------------------------
__device__ __forceinline__ float to_tf32(float x) {
    uint32_t u;
    asm("cvt.rna.tf32.f32 %0, %1;" : "=r"(u) : "f"(x));
    return __uint_as_float(u);
}

__device__ __forceinline__ float softcapf(float x) {
    return CAPV * tanhf(x * (1.0f / CAPV));
}

__device__ __forceinline__ float logsigf(float x) {
    return (x >= 0.0f) ? -log1pf(expf(-x)) : (x - log1pf(expf(x)));
}

__device__ __forceinline__ float sigmoidf_(float x) {
    return 1.0f / (1.0f + expf(-x));
}

__device__ __forceinline__ void cpasync16(uint32_t dst, const void* src) {
    asm volatile("cp.async.cg.shared.global [%0], [%1], 16;\n"
                 :: "r"(dst), "l"(src));
}

#define MMA_TF32(acc, a0, a1, a2, a3, b0, b1)                                  \
    asm volatile(                                                              \
        "mma.sync.aligned.m16n8k8.row.col.f32.tf32.tf32.f32 "                  \
        "{%0,%1,%2,%3}, {%4,%5,%6,%7}, {%8,%9}, {%0,%1,%2,%3};\n"              \
        : "+f"(acc[0]), "+f"(acc[1]), "+f"(acc[2]), "+f"(acc[3])               \
        : "r"(a0), "r"(a1), "r"(a2), "r"(a3), "r"(b0), "r"(b1))

// ---------------------------------------------------------------------------
// 3xTF32 split-precision GEMM: C[M,N] = A[M,K] @ B[K,N] (+ Res), ~fp32 accuracy.
// Operands stay raw fp32 in smem; hi/lo split happens at fragment load:
//   hi = tf32(v), lo = tf32(v - hi);  acc += hi*hi + hi*lo + lo*hi
// CTA 64x64x32, 128 threads (4 warps, 2x2), warp tile 32x32, 2-stage cp.async.
// Requires: M%64==0, N%64==0, K%32==0, 16B-aligned pointers.
// ---------------------------------------------------------------------------
#define BM 64
#define BN 64
#define BK 32
#define BKP 36   // 144B rows — conflict-free a-frag LDS
#define BNP 72   // 288B rows — conflict-free b-frag LDS

__global__ __launch_bounds__(128) void gemm_3xtf32_kernel(
    const float* __restrict__ A, const float* __restrict__ B,
    float* __restrict__ C, const float* __restrict__ Res,
    int M, int N, int K)
{
    __shared__ float As[2][BM][BKP];
    __shared__ float Bs[2][BK][BNP];

    const int tid  = threadIdx.x;
    const int m0   = blockIdx.y * BM;
    const int n0   = blockIdx.x * BN;
    const int warp = tid >> 5;
    const int lane = tid & 31;
    const int wm   = (warp >> 1) * 32;
    const int wn   = (warp & 1) * 32;
    const int gid  = lane >> 2;          // 0..7
    const int tig  = lane & 3;           // 0..3

    int a_r[4], a_c[4], b_r[4], b_c[4];
    uint32_t a_dst[2][4], b_dst[2][4];
#pragma unroll
    for (int it = 0; it < 4; ++it) {
        int idx = tid + it * 128;
        a_r[it] = idx >> 3;        a_c[it] = (idx & 7) * 4;
        b_r[it] = idx >> 4;        b_c[it] = (idx & 15) * 4;
#pragma unroll
        for (int s = 0; s < 2; ++s) {
            a_dst[s][it] = (uint32_t)__cvta_generic_to_shared(&As[s][a_r[it]][a_c[it]]);
            b_dst[s][it] = (uint32_t)__cvta_generic_to_shared(&Bs[s][b_r[it]][b_c[it]]);
        }
    }

    float acc[2][4][4];
#pragma unroll
    for (int mt = 0; mt < 2; ++mt)
#pragma unroll
        for (int nt = 0; nt < 4; ++nt)
#pragma unroll
            for (int r = 0; r < 4; ++r) acc[mt][nt][r] = 0.0f;

    const int nk = K / BK;

#pragma unroll
    for (int it = 0; it < 4; ++it) {
        cpasync16(a_dst[0][it], A + (size_t)(m0 + a_r[it]) * K + a_c[it]);
        cpasync16(b_dst[0][it], B + (size_t)b_r[it] * N + n0 + b_c[it]);
    }
    asm volatile("cp.async.commit_group;\n");

    for (int kt = 0; kt < nk; ++kt) {
        const int cur = kt & 1;
        if (kt + 1 < nk) {
            const int nxt = cur ^ 1;
            const int koff = (kt + 1) * BK;
#pragma unroll
            for (int it = 0; it < 4; ++it) {
                cpasync16(a_dst[nxt][it],
                          A + (size_t)(m0 + a_r[it]) * K + koff + a_c[it]);
                cpasync16(b_dst[nxt][it],
                          B + (size_t)(koff + b_r[it]) * N + n0 + b_c[it]);
            }
            asm volatile("cp.async.commit_group;\n");
            asm volatile("cp.async.wait_group 1;\n");
        } else {
            asm volatile("cp.async.wait_group 0;\n");
        }
        __syncthreads();

#pragma unroll
        for (int kk = 0; kk < BK; kk += 8) {
            uint32_t ah[2][4], al[2][4], bh[4][2], bl[4][2];
#pragma unroll
            for (int mt = 0; mt < 2; ++mt) {
                int r = wm + mt * 16 + gid;
                float v0 = As[cur][r    ][kk + tig];
                float v1 = As[cur][r + 8][kk + tig];
                float v2 = As[cur][r    ][kk + tig + 4];
                float v3 = As[cur][r + 8][kk + tig + 4];
                float h0 = to_tf32(v0), h1 = to_tf32(v1);
                float h2 = to_tf32(v2), h3 = to_tf32(v3);
                ah[mt][0] = __float_as_uint(h0);
                ah[mt][1] = __float_as_uint(h1);
                ah[mt][2] = __float_as_uint(h2);
                ah[mt][3] = __float_as_uint(h3);
                al[mt][0] = __float_as_uint(to_tf32(v0 - h0));
                al[mt][1] = __float_as_uint(to_tf32(v1 - h1));
                al[mt][2] = __float_as_uint(to_tf32(v2 - h2));
                al[mt][3] = __float_as_uint(to_tf32(v3 - h3));
            }
#pragma unroll
            for (int nt = 0; nt < 4; ++nt) {
                int c = wn + nt * 8 + gid;
                float v0 = Bs[cur][kk + tig    ][c];
                float v1 = Bs[cur][kk + tig + 4][c];
                float h0 = to_tf32(v0), h1 = to_tf32(v1);
                bh[nt][0] = __float_as_uint(h0);
                bh[nt][1] = __float_as_uint(h1);
                bl[nt][0] = __float_as_uint(to_tf32(v0 - h0));
                bl[nt][1] = __float_as_uint(to_tf32(v1 - h1));
            }
#pragma unroll
            for (int mt = 0; mt < 2; ++mt)
#pragma unroll
                for (int nt = 0; nt < 4; ++nt) {
                    // cross terms first, hi*hi last (all fp32 accumulate)
                    MMA_TF32(acc[mt][nt], ah[mt][0], ah[mt][1], ah[mt][2], ah[mt][3],
                             bl[nt][0], bl[nt][1]);
                    MMA_TF32(acc[mt][nt], al[mt][0], al[mt][1], al[mt][2], al[mt][3],
                             bh[nt][0], bh[nt][1]);
                    MMA_TF32(acc[mt][nt], ah[mt][0], ah[mt][1], ah[mt][2], ah[mt][3],
                             bh[nt][0], bh[nt][1]);
                }
        }
        __syncthreads();
    }

#pragma unroll
    for (int mt = 0; mt < 2; ++mt) {
#pragma unroll
        for (int nt = 0; nt < 4; ++nt) {
            int r0 = m0 + wm + mt * 16 + gid;
            int c  = n0 + wn + nt * 8 + tig * 2;
            float2 v0 = make_float2(acc[mt][nt][0], acc[mt][nt][1]);
            float2 v1 = make_float2(acc[mt][nt][2], acc[mt][nt][3]);
            if (Res != nullptr) {
                float2 r = *reinterpret_cast<const float2*>(Res + (size_t)r0 * N + c);
                v0.x += r.x; v0.y += r.y;
                r = *reinterpret_cast<const float2*>(Res + (size_t)(r0 + 8) * N + c);
                v1.x += r.x; v1.y += r.y;
            }
            *reinterpret_cast<float2*>(C + (size_t)r0 * N + c)       = v0;
            *reinterpret_cast<float2*>(C + (size_t)(r0 + 8) * N + c) = v1;
        }
    }
}

// ---------------------------------------------------------------------------
// RMSNorm (H=512, block=128), pure fp32.
// ---------------------------------------------------------------------------
__global__ __launch_bounds__(128) void rmsnorm_kernel(
    const float* __restrict__ x, const float* __restrict__ w,
    float* __restrict__ out)
{
    const int row = blockIdx.x, tid = threadIdx.x;
    float4 v = reinterpret_cast<const float4*>(x + (size_t)row * HDIM)[tid];
    float ss = v.x * v.x + v.y * v.y + v.z * v.z + v.w * v.w;
#pragma unroll
    for (int o = 16; o; o >>= 1) ss += __shfl_xor_sync(0xffffffffu, ss, o);
    __shared__ float sred[4];
    if ((tid & 31) == 0) sred[tid >> 5] = ss;
    __syncthreads();
    float tot = sred[0] + sred[1] + sred[2] + sred[3];
    float inv = rsqrtf(tot * (1.0f / (float)HDIM) + EPSV);
    float4 wv = reinterpret_cast<const float4*>(w)[tid];
    float4 o4 = make_float4(v.x * inv * wv.x, v.y * inv * wv.y,
                            v.z * inv * wv.z, v.w * inv * wv.w);
    reinterpret_cast<float4*>(out + (size_t)row * HDIM)[tid] = o4;
}

// ---------------------------------------------------------------------------
// Pack [Wi | Wf | zeros] into g_wif (raw fp32; GEMM handles precision)
// ---------------------------------------------------------------------------
__global__ void pack_wif_kernel(const float* __restrict__ Wi,
                                const float* __restrict__ Wf,
                                float* __restrict__ out)
{
    int blk = blockIdx.x;           // l*HDIM + kk
    int col = threadIdx.x;          // 0..63
    float val = 0.0f;
    if (col < NHEAD)            val = Wi[(size_t)blk * NHEAD + col];
    else if (col < 2 * NHEAD)   val = Wf[(size_t)blk * NHEAD + (col - NHEAD)];
    out[(size_t)blk * 64 + col] = val;
}

// ---------------------------------------------------------------------------
// mLSTM step (zero state) + per-head RMSNorm + output gate. Pure fp32.
// One block per token, one warp per head (block = 256 = 8 warps).
// ---------------------------------------------------------------------------
__global__ __launch_bounds__(256) void mlstm_kernel(
    const float* __restrict__ q, const float* __restrict__ k,
    const float* __restrict__ v, const float* __restrict__ ogp,
    const float* __restrict__ ifp,           // [NTOK,64]: cols 0..7 = i, 8..15 = f
    const float* __restrict__ bi, const float* __restrict__ bf,
    const float* __restrict__ mhw,           // [NHEAD, DHV]
    float* __restrict__ hv)
{
    const int t = blockIdx.x;
    const int h = threadIdx.x >> 5;
    const int lane = threadIdx.x & 31;

    float ip = softcapf(ifp[(size_t)t * 64 + h]      + bi[h]);
    float fp = softcapf(ifp[(size_t)t * 64 + 8 + h]  + bf[h]);
    float flog = logsigf(fp);
    float m = fmaxf(flog, ip);
    float iact = expf(ip - m);

    float qd = q[(size_t)t * QKDIM + h * DHQK + lane];
    float kd = k[(size_t)t * QKDIM + h * DHQK + lane];
    float s = qd * kd;
#pragma unroll
    for (int o = 16; o; o >>= 1) s += __shfl_xor_sync(0xffffffffu, s, o);
    s *= 0.17677669529663687f;  // 32^-0.5

    float qn = iact * s;
    float denom = fmaxf(fabsf(qn), expf(-m)) + EPSV;
    float c = iact * s / denom;

    const int base = t * VDIM + h * DHV;
    float v0 = v[base + lane], v1 = v[base + 32 + lane];
    float h0 = c * v0, h1 = c * v1;

    float ms = h0 * h0 + h1 * h1;
#pragma unroll
    for (int o = 16; o; o >>= 1) ms += __shfl_xor_sync(0xffffffffu, ms, o);
    float inv = rsqrtf(ms * (1.0f / (float)DHV) + EPSV);

    float w0 = mhw[h * DHV + lane],      w1 = mhw[h * DHV + 32 + lane];
    float g0 = sigmoidf_(ogp[base + lane]);
    float g1 = sigmoidf_(ogp[base + 32 + lane]);
    hv[base + lane]      = h0 * inv * w0 * g0;
    hv[base + 32 + lane] = h1 * inv * w1 * g1;
}

// ---------------------------------------------------------------------------
// SwiGLU activation: g = silu(g) * up  (pure fp32)
// ---------------------------------------------------------------------------
__global__ __launch_bounds__(256) void silu_mul_kernel(
    float* __restrict__ g, const float* __restrict__ up, int n4)
{
    int i = blockIdx.x * blockDim.x + threadIdx.x;
    if (i >= n4) return;
    float4 gv = reinterpret_cast<float4*>(g)[i];
    float4 uv = reinterpret_cast<const float4*>(up)[i];
    gv.x = gv.x * sigmoidf_(gv.x) * uv.x;
    gv.y = gv.y * sigmoidf_(gv.y) * uv.y;
    gv.z = gv.z * sigmoidf_(gv.z) * uv.z;
    gv.w = gv.w * sigmoidf_(gv.w) * uv.w;
    reinterpret_cast<float4*>(g)[i] = gv;
}

// ---------------------------------------------------------------------------
// Host launcher
// ---------------------------------------------------------------------------
static inline float* sym_addr(const void* sym) {
    void* p = nullptr;
    cudaGetSymbolAddress(&p, sym);
    return reinterpret_cast<float*>(p);
}

static inline void gemm(const float* A, const float* B, float* C,
                        const float* Res, int M, int N, int K) {
    dim3 grid(N / BN, M / BM);
    gemm_3xtf32_kernel<<<grid, 128>>>(A, B, C, Res, M, N, K);
}

extern "C" void kernel_launch(void* const* d_in, const int* in_sizes, int n_in,
                              void* d_out, int out_size)
{
    (void)in_sizes; (void)n_in; (void)out_size;
    const float* u       = (const float*)d_in[0];
    const float* norm1_w = (const float*)d_in[1];
    const float* Wq      = (const float*)d_in[2];
    const float* Wk      = (const float*)d_in[3];
    const float* Wv      = (const float*)d_in[4];
    const float* Wi      = (const float*)d_in[5];
    const float* bi      = (const float*)d_in[6];
    const float* Wf      = (const float*)d_in[7];
    const float* bf      = (const float*)d_in[8];
    const float* mh_w    = (const float*)d_in[9];
    const float* Wog     = (const float*)d_in[10];
    const float* Wout    = (const float*)d_in[11];
    const float* norm2_w = (const float*)d_in[12];
    const float* W_up    = (const float*)d_in[13];
    const float* W_gate  = (const float*)d_in[14];
    const float* W_down  = (const float*)d_in[15];
    const float* final_w = (const float*)d_in[16];
    float* out = (float*)d_out;

    float* x    = sym_addr(g_x);
    float* xn   = sym_addr(g_xn);
    float* qb   = sym_addr(g_q);
    float* kb   = sym_addr(g_k);
    float* vb   = sym_addr(g_v);
    float* ogb  = sym_addr(g_og);
    float* ifb  = sym_addr(g_if);
    float* hvb  = sym_addr(g_hv);
    float* gb   = sym_addr(g_gate);
    float* ub   = sym_addr(g_up);
    float* wif  = sym_addr(g_wif);

    cudaMemcpyAsync(x, u, (size_t)NTOK * HDIM * sizeof(float),
                    cudaMemcpyDeviceToDevice, 0);

    pack_wif_kernel<<<LAYERS * HDIM, 64>>>(Wi, Wf, wif);

    for (int l = 0; l < LAYERS; ++l) {
        const float* wq   = Wq     + (size_t)l * HDIM * QKDIM;
        const float* wk   = Wk     + (size_t)l * HDIM * QKDIM;
        const float* wv   = Wv     + (size_t)l * HDIM * VDIM;
        const float* wog  = Wog    + (size_t)l * HDIM * VDIM;
        const float* wo   = Wout   + (size_t)l * VDIM * HDIM;
        const float* wu   = W_up   + (size_t)l * HDIM * FDIM;
        const float* wg   = W_gate + (size_t)l * HDIM * FDIM;
        const float* wd   = W_down + (size_t)l * FDIM * HDIM;
        const float* wifl = wif    + (size_t)l * HDIM * 64;

        // --- mLSTM block ---
        rmsnorm_kernel<<<NTOK, 128>>>(x, norm1_w + l * HDIM, xn);
        gemm(xn, wq,   qb,  nullptr, NTOK, QKDIM, HDIM);
        gemm(xn, wk,   kb,  nullptr, NTOK, QKDIM, HDIM);
        gemm(xn, wv,   vb,  nullptr, NTOK, VDIM,  HDIM);
        gemm(xn, wog,  ogb, nullptr, NTOK, VDIM,  HDIM);
        gemm(xn, wifl, ifb, nullptr, NTOK, 64,    HDIM);
        mlstm_kernel<<<NTOK, 256>>>(qb, kb, vb, ogb, ifb,
                                    bi + l * NHEAD, bf + l * NHEAD,
                                    mh_w + (size_t)l * NHEAD * DHV, hvb);
        gemm(hvb, wo, x, x, NTOK, HDIM, VDIM);   // x += hv @ Wout

        // --- FFN block ---
        rmsnorm_kernel<<<NTOK, 128>>>(x, norm2_w + l * HDIM, xn);
        gemm(xn, wg, gb, nullptr, NTOK, FDIM, HDIM);
        gemm(xn, wu, ub, nullptr, NTOK, FDIM, HDIM);
        silu_mul_kernel<<<(NTOK * FDIM / 4 + 255) / 256, 256>>>(gb, ub, NTOK * FDIM / 4);
        gemm(gb, wd, x, x, NTOK, HDIM, FDIM);    // x += act @ W_down
    }

    rmsnorm_kernel<<<NTOK, 128>>>(x, final_w, out);
}

// round 8
// speedup vs baseline: 1.1084x; 1.1084x over previous
#include <cuda_runtime.h>
#include <cuda_bf16.h>
#include <cstdint>

// ---------------------------------------------------------------------------
// Problem constants
// ---------------------------------------------------------------------------
#define LAYERS 4
#define HDIM   512
#define NHEAD  8
#define DHQK   32
#define DHV    64
#define QKDIM  (NHEAD * DHQK)   // 256
#define VDIM   (NHEAD * DHV)    // 512
#define FDIM   1408
#define NTOK   2048              // B*P = 8*256
#define CAPV   15.0f
#define EPSV   1e-6f

// ---------------------------------------------------------------------------
// Device scratch (static: no allocation allowed)
// ---------------------------------------------------------------------------
__device__ float g_x   [NTOK * HDIM];
__device__ float g_xn  [NTOK * HDIM];
__device__ float g_q   [NTOK * QKDIM];
__device__ float g_k   [NTOK * QKDIM];
__device__ float g_v   [NTOK * VDIM];
__device__ float g_og  [NTOK * VDIM];
__device__ float g_if  [NTOK * 64];
__device__ float g_hv  [NTOK * VDIM];
__device__ float g_gate[NTOK * FDIM];
__device__ float g_up  [NTOK * FDIM];
__device__ float g_wif [LAYERS * HDIM * 64];   // packed [Wi | Wf | 0...] per layer

// ---------------------------------------------------------------------------
// Helpers
// ---------------------------------------------------------------------------
__device__ __forceinline__ float to_tf32(float x) {
    uint32_t u;
    asm("cvt.rna.tf32.f32 %0, %1;" : "=r"(u) : "f"(x));
    return __uint_as_float(u);
}

__device__ __forceinline__ float softcapf(float x) {
    return CAPV * tanhf(x * (1.0f / CAPV));
}

__device__ __forceinline__ float logsigf(float x) {
    return (x >= 0.0f) ? -log1pf(expf(-x)) : (x - log1pf(expf(x)));
}

__device__ __forceinline__ float sigmoidf_(float x) {
    return 1.0f / (1.0f + expf(-x));
}

__device__ __forceinline__ void cpasync16(uint32_t dst, const void* src) {
    asm volatile("cp.async.cg.shared.global [%0], [%1], 16;\n"
                 :: "r"(dst), "l"(src));
}

#define MMA_TF32(acc, a0, a1, a2, a3, b0, b1)                                  \
    asm volatile(                                                              \
        "mma.sync.aligned.m16n8k8.row.col.f32.tf32.tf32.f32 "                  \
        "{%0,%1,%2,%3}, {%4,%5,%6,%7}, {%8,%9}, {%0,%1,%2,%3};\n"              \
        : "+f"(acc[0]), "+f"(acc[1]), "+f"(acc[2]), "+f"(acc[3])               \
        : "r"(a0), "r"(a1), "r"(a2), "r"(a3), "r"(b0), "r"(b1))

// ---------------------------------------------------------------------------
// Multi-segment 3xTF32 GEMM.
// Several GEMMs C_s = A @ B_s (+ Res_s) sharing the same A[M,K] run in ONE
// launch: blockIdx.x enumerates 64-wide n-blocks across all segments.
// Per-segment: B (K x N_s row-major), C (M x N_s), optional Res, width N_s.
// Precision: operands raw fp32 in smem; hi/lo tf32 split at fragment load;
// acc += ah*bl + al*bh + ah*bh  (~fp32 GEMM accuracy).
// CTA 64x64x32, 128 threads (4 warps 2x2), 2-stage cp.async.
// ---------------------------------------------------------------------------
#define MAXSEG 5
struct GemmSeg {
    const float* B;
    float*       C;
    const float* Res;   // nullptr = no residual add
    int          N;     // column width of this segment
    int          nstart;// first global n-block of this segment
};
struct GemmDesc {
    int nseg;
    GemmSeg seg[MAXSEG];
};

#define BM 64
#define BN 64
#define BK 32
#define BKP 36   // 144B rows — conflict-free a-frag LDS
#define BNP 72   // 288B rows — conflict-free b-frag LDS

__global__ __launch_bounds__(128) void gemm_3xtf32_multi_kernel(
    const float* __restrict__ A, int M, int K, GemmDesc d)
{
    __shared__ float As[2][BM][BKP];
    __shared__ float Bs[2][BK][BNP];

    // --- segment lookup (uniform per CTA) ---
    const int nblk = blockIdx.x;
    int si = 0;
#pragma unroll
    for (int t = 1; t < MAXSEG; ++t)
        if (t < d.nseg && nblk >= d.seg[t].nstart) si = t;
    const float* __restrict__ B   = d.seg[si].B;
    float*       __restrict__ C   = d.seg[si].C;
    const float* __restrict__ Res = d.seg[si].Res;
    const int N  = d.seg[si].N;
    const int n0 = (nblk - d.seg[si].nstart) * BN;
    const int m0 = blockIdx.y * BM;

    const int tid  = threadIdx.x;
    const int warp = tid >> 5;
    const int lane = tid & 31;
    const int wm   = (warp >> 1) * 32;
    const int wn   = (warp & 1) * 32;
    const int gid  = lane >> 2;          // 0..7
    const int tig  = lane & 3;           // 0..3

    int a_r[4], a_c[4], b_r[4], b_c[4];
    uint32_t a_dst[2][4], b_dst[2][4];
#pragma unroll
    for (int it = 0; it < 4; ++it) {
        int idx = tid + it * 128;
        a_r[it] = idx >> 3;        a_c[it] = (idx & 7) * 4;
        b_r[it] = idx >> 4;        b_c[it] = (idx & 15) * 4;
#pragma unroll
        for (int s = 0; s < 2; ++s) {
            a_dst[s][it] = (uint32_t)__cvta_generic_to_shared(&As[s][a_r[it]][a_c[it]]);
            b_dst[s][it] = (uint32_t)__cvta_generic_to_shared(&Bs[s][b_r[it]][b_c[it]]);
        }
    }

    float acc[2][4][4];
#pragma unroll
    for (int mt = 0; mt < 2; ++mt)
#pragma unroll
        for (int nt = 0; nt < 4; ++nt)
#pragma unroll
            for (int r = 0; r < 4; ++r) acc[mt][nt][r] = 0.0f;

    const int nk = K / BK;

#pragma unroll
    for (int it = 0; it < 4; ++it) {
        cpasync16(a_dst[0][it], A + (size_t)(m0 + a_r[it]) * K + a_c[it]);
        cpasync16(b_dst[0][it], B + (size_t)b_r[it] * N + n0 + b_c[it]);
    }
    asm volatile("cp.async.commit_group;\n");

    for (int kt = 0; kt < nk; ++kt) {
        const int cur = kt & 1;
        if (kt + 1 < nk) {
            const int nxt = cur ^ 1;
            const int koff = (kt + 1) * BK;
#pragma unroll
            for (int it = 0; it < 4; ++it) {
                cpasync16(a_dst[nxt][it],
                          A + (size_t)(m0 + a_r[it]) * K + koff + a_c[it]);
                cpasync16(b_dst[nxt][it],
                          B + (size_t)(koff + b_r[it]) * N + n0 + b_c[it]);
            }
            asm volatile("cp.async.commit_group;\n");
            asm volatile("cp.async.wait_group 1;\n");
        } else {
            asm volatile("cp.async.wait_group 0;\n");
        }
        __syncthreads();

#pragma unroll
        for (int kk = 0; kk < BK; kk += 8) {
            uint32_t ah[2][4], al[2][4], bh[4][2], bl[4][2];
#pragma unroll
            for (int mt = 0; mt < 2; ++mt) {
                int r = wm + mt * 16 + gid;
                float v0 = As[cur][r    ][kk + tig];
                float v1 = As[cur][r + 8][kk + tig];
                float v2 = As[cur][r    ][kk + tig + 4];
                float v3 = As[cur][r + 8][kk + tig + 4];
                float h0 = to_tf32(v0), h1 = to_tf32(v1);
                float h2 = to_tf32(v2), h3 = to_tf32(v3);
                ah[mt][0] = __float_as_uint(h0);
                ah[mt][1] = __float_as_uint(h1);
                ah[mt][2] = __float_as_uint(h2);
                ah[mt][3] = __float_as_uint(h3);
                al[mt][0] = __float_as_uint(to_tf32(v0 - h0));
                al[mt][1] = __float_as_uint(to_tf32(v1 - h1));
                al[mt][2] = __float_as_uint(to_tf32(v2 - h2));
                al[mt][3] = __float_as_uint(to_tf32(v3 - h3));
            }
#pragma unroll
            for (int nt = 0; nt < 4; ++nt) {
                int c = wn + nt * 8 + gid;
                float v0 = Bs[cur][kk + tig    ][c];
                float v1 = Bs[cur][kk + tig + 4][c];
                float h0 = to_tf32(v0), h1 = to_tf32(v1);
                bh[nt][0] = __float_as_uint(h0);
                bh[nt][1] = __float_as_uint(h1);
                bl[nt][0] = __float_as_uint(to_tf32(v0 - h0));
                bl[nt][1] = __float_as_uint(to_tf32(v1 - h1));
            }
#pragma unroll
            for (int mt = 0; mt < 2; ++mt)
#pragma unroll
                for (int nt = 0; nt < 4; ++nt) {
                    MMA_TF32(acc[mt][nt], ah[mt][0], ah[mt][1], ah[mt][2], ah[mt][3],
                             bl[nt][0], bl[nt][1]);
                    MMA_TF32(acc[mt][nt], al[mt][0], al[mt][1], al[mt][2], al[mt][3],
                             bh[nt][0], bh[nt][1]);
                    MMA_TF32(acc[mt][nt], ah[mt][0], ah[mt][1], ah[mt][2], ah[mt][3],
                             bh[nt][0], bh[nt][1]);
                }
        }
        __syncthreads();
    }

#pragma unroll
    for (int mt = 0; mt < 2; ++mt) {
#pragma unroll
        for (int nt = 0; nt < 4; ++nt) {
            int r0 = m0 + wm + mt * 16 + gid;
            int c  = n0 + wn + nt * 8 + tig * 2;
            float2 v0 = make_float2(acc[mt][nt][0], acc[mt][nt][1]);
            float2 v1 = make_float2(acc[mt][nt][2], acc[mt][nt][3]);
            if (Res != nullptr) {
                float2 r = *reinterpret_cast<const float2*>(Res + (size_t)r0 * N + c);
                v0.x += r.x; v0.y += r.y;
                r = *reinterpret_cast<const float2*>(Res + (size_t)(r0 + 8) * N + c);
                v1.x += r.x; v1.y += r.y;
            }
            *reinterpret_cast<float2*>(C + (size_t)r0 * N + c)       = v0;
            *reinterpret_cast<float2*>(C + (size_t)(r0 + 8) * N + c) = v1;
        }
    }
}

// ---------------------------------------------------------------------------
// RMSNorm (H=512, block=128), pure fp32.
// ---------------------------------------------------------------------------
__global__ __launch_bounds__(128) void rmsnorm_kernel(
    const float* __restrict__ x, const float* __restrict__ w,
    float* __restrict__ out)
{
    const int row = blockIdx.x, tid = threadIdx.x;
    float4 v = reinterpret_cast<const float4*>(x + (size_t)row * HDIM)[tid];
    float ss = v.x * v.x + v.y * v.y + v.z * v.z + v.w * v.w;
#pragma unroll
    for (int o = 16; o; o >>= 1) ss += __shfl_xor_sync(0xffffffffu, ss, o);
    __shared__ float sred[4];
    if ((tid & 31) == 0) sred[tid >> 5] = ss;
    __syncthreads();
    float tot = sred[0] + sred[1] + sred[2] + sred[3];
    float inv = rsqrtf(tot * (1.0f / (float)HDIM) + EPSV);
    float4 wv = reinterpret_cast<const float4*>(w)[tid];
    float4 o4 = make_float4(v.x * inv * wv.x, v.y * inv * wv.y,
                            v.z * inv * wv.z, v.w * inv * wv.w);
    reinterpret_cast<float4*>(out + (size_t)row * HDIM)[tid] = o4;
}

// ---------------------------------------------------------------------------
// Pack [Wi | Wf | zeros] into g_wif (raw fp32)
// ---------------------------------------------------------------------------
__global__ void pack_wif_kernel(const float* __restrict__ Wi,
                                const float* __restrict__ Wf,
                                float* __restrict__ out)
{
    int blk = blockIdx.x;           // l*HDIM + kk
    int col = threadIdx.x;          // 0..63
    float val = 0.0f;
    if (col < NHEAD)            val = Wi[(size_t)blk * NHEAD + col];
    else if (col < 2 * NHEAD)   val = Wf[(size_t)blk * NHEAD + (col - NHEAD)];
    out[(size_t)blk * 64 + col] = val;
}

// ---------------------------------------------------------------------------
// mLSTM step (zero state) + per-head RMSNorm + output gate. Pure fp32.
// One block per token, one warp per head (block = 256 = 8 warps).
// ---------------------------------------------------------------------------
__global__ __launch_bounds__(256) void mlstm_kernel(
    const float* __restrict__ q, const float* __restrict__ k,
    const float* __restrict__ v, const float* __restrict__ ogp,
    const float* __restrict__ ifp,           // [NTOK,64]: cols 0..7 = i, 8..15 = f
    const float* __restrict__ bi, const float* __restrict__ bf,
    const float* __restrict__ mhw,           // [NHEAD, DHV]
    float* __restrict__ hv)
{
    const int t = blockIdx.x;
    const int h = threadIdx.x >> 5;
    const int lane = threadIdx.x & 31;

    float ip = softcapf(ifp[(size_t)t * 64 + h]      + bi[h]);
    float fp = softcapf(ifp[(size_t)t * 64 + 8 + h]  + bf[h]);
    float flog = logsigf(fp);
    float m = fmaxf(flog, ip);
    float iact = expf(ip - m);

    float qd = q[(size_t)t * QKDIM + h * DHQK + lane];
    float kd = k[(size_t)t * QKDIM + h * DHQK + lane];
    float s = qd * kd;
#pragma unroll
    for (int o = 16; o; o >>= 1) s += __shfl_xor_sync(0xffffffffu, s, o);
    s *= 0.17677669529663687f;  // 32^-0.5

    float qn = iact * s;
    float denom = fmaxf(fabsf(qn), expf(-m)) + EPSV;
    float c = iact * s / denom;

    const int base = t * VDIM + h * DHV;
    float v0 = v[base + lane], v1 = v[base + 32 + lane];
    float h0 = c * v0, h1 = c * v1;

    float ms = h0 * h0 + h1 * h1;
#pragma unroll
    for (int o = 16; o; o >>= 1) ms += __shfl_xor_sync(0xffffffffu, ms, o);
    float inv = rsqrtf(ms * (1.0f / (float)DHV) + EPSV);

    float w0 = mhw[h * DHV + lane],      w1 = mhw[h * DHV + 32 + lane];
    float g0 = sigmoidf_(ogp[base + lane]);
    float g1 = sigmoidf_(ogp[base + 32 + lane]);
    hv[base + lane]      = h0 * inv * w0 * g0;
    hv[base + 32 + lane] = h1 * inv * w1 * g1;
}

// ---------------------------------------------------------------------------
// SwiGLU activation: g = silu(g) * up  (pure fp32)
// ---------------------------------------------------------------------------
__global__ __launch_bounds__(256) void silu_mul_kernel(
    float* __restrict__ g, const float* __restrict__ up, int n4)
{
    int i = blockIdx.x * blockDim.x + threadIdx.x;
    if (i >= n4) return;
    float4 gv = reinterpret_cast<float4*>(g)[i];
    float4 uv = reinterpret_cast<const float4*>(up)[i];
    gv.x = gv.x * sigmoidf_(gv.x) * uv.x;
    gv.y = gv.y * sigmoidf_(gv.y) * uv.y;
    gv.z = gv.z * sigmoidf_(gv.z) * uv.z;
    gv.w = gv.w * sigmoidf_(gv.w) * uv.w;
    reinterpret_cast<float4*>(g)[i] = gv;
}

// ---------------------------------------------------------------------------
// Host launcher
// ---------------------------------------------------------------------------
static inline float* sym_addr(const void* sym) {
    void* p = nullptr;
    cudaGetSymbolAddress(&p, sym);
    return reinterpret_cast<float*>(p);
}

static inline void gemm_multi(const float* A, int M, int K, const GemmDesc& d) {
    int nb = d.seg[d.nseg - 1].nstart + d.seg[d.nseg - 1].N / BN;
    dim3 grid(nb, M / BM);
    gemm_3xtf32_multi_kernel<<<grid, 128>>>(A, M, K, d);
}

extern "C" void kernel_launch(void* const* d_in, const int* in_sizes, int n_in,
                              void* d_out, int out_size)
{
    (void)in_sizes; (void)n_in; (void)out_size;
    const float* u       = (const float*)d_in[0];
    const float* norm1_w = (const float*)d_in[1];
    const float* Wq      = (const float*)d_in[2];
    const float* Wk      = (const float*)d_in[3];
    const float* Wv      = (const float*)d_in[4];
    const float* Wi      = (const float*)d_in[5];
    const float* bi      = (const float*)d_in[6];
    const float* Wf      = (const float*)d_in[7];
    const float* bf      = (const float*)d_in[8];
    const float* mh_w    = (const float*)d_in[9];
    const float* Wog     = (const float*)d_in[10];
    const float* Wout    = (const float*)d_in[11];
    const float* norm2_w = (const float*)d_in[12];
    const float* W_up    = (const float*)d_in[13];
    const float* W_gate  = (const float*)d_in[14];
    const float* W_down  = (const float*)d_in[15];
    const float* final_w = (const float*)d_in[16];
    float* out = (float*)d_out;

    float* x    = sym_addr(g_x);
    float* xn   = sym_addr(g_xn);
    float* qb   = sym_addr(g_q);
    float* kb   = sym_addr(g_k);
    float* vb   = sym_addr(g_v);
    float* ogb  = sym_addr(g_og);
    float* ifb  = sym_addr(g_if);
    float* hvb  = sym_addr(g_hv);
    float* gb   = sym_addr(g_gate);
    float* ub   = sym_addr(g_up);
    float* wif  = sym_addr(g_wif);

    cudaMemcpyAsync(x, u, (size_t)NTOK * HDIM * sizeof(float),
                    cudaMemcpyDeviceToDevice, 0);

    pack_wif_kernel<<<LAYERS * HDIM, 64>>>(Wi, Wf, wif);

    for (int l = 0; l < LAYERS; ++l) {
        const float* wq   = Wq     + (size_t)l * HDIM * QKDIM;
        const float* wk   = Wk     + (size_t)l * HDIM * QKDIM;
        const float* wv   = Wv     + (size_t)l * HDIM * VDIM;
        const float* wog  = Wog    + (size_t)l * HDIM * VDIM;
        const float* wo   = Wout   + (size_t)l * VDIM * HDIM;
        const float* wu   = W_up   + (size_t)l * HDIM * FDIM;
        const float* wg   = W_gate + (size_t)l * HDIM * FDIM;
        const float* wd   = W_down + (size_t)l * FDIM * HDIM;
        const float* wifl = wif    + (size_t)l * HDIM * 64;

        // --- mLSTM block ---
        rmsnorm_kernel<<<NTOK, 128>>>(x, norm1_w + l * HDIM, xn);

        // q | k | v | og | if  in one launch (all share A=xn, K=512)
        GemmDesc d1;
        d1.nseg = 5;
        d1.seg[0] = { wq,   qb,  nullptr, QKDIM, 0  };           // 4 blocks
        d1.seg[1] = { wk,   kb,  nullptr, QKDIM, 4  };           // 4
        d1.seg[2] = { wv,   vb,  nullptr, VDIM,  8  };           // 8
        d1.seg[3] = { wog,  ogb, nullptr, VDIM,  16 };           // 8
        d1.seg[4] = { wifl, ifb, nullptr, 64,    24 };           // 1  -> 25 total
        gemm_multi(xn, NTOK, HDIM, d1);

        mlstm_kernel<<<NTOK, 256>>>(qb, kb, vb, ogb, ifb,
                                    bi + l * NHEAD, bf + l * NHEAD,
                                    mh_w + (size_t)l * NHEAD * DHV, hvb);

        GemmDesc d2;                  // x += hv @ Wout
        d2.nseg = 1;
        d2.seg[0] = { wo, x, x, HDIM, 0 };
        gemm_multi(hvb, NTOK, VDIM, d2);

        // --- FFN block ---
        rmsnorm_kernel<<<NTOK, 128>>>(x, norm2_w + l * HDIM, xn);

        GemmDesc d3;                  // gate | up in one launch
        d3.nseg = 2;
        d3.seg[0] = { wg, gb, nullptr, FDIM, 0  };               // 22 blocks
        d3.seg[1] = { wu, ub, nullptr, FDIM, 22 };               // 22 -> 44 total
        gemm_multi(xn, NTOK, HDIM, d3);

        silu_mul_kernel<<<(NTOK * FDIM / 4 + 255) / 256, 256>>>(gb, ub, NTOK * FDIM / 4);

        GemmDesc d4;                  // x += act @ W_down
        d4.nseg = 1;
        d4.seg[0] = { wd, x, x, HDIM, 0 };
        gemm_multi(gb, NTOK, FDIM, d4);
    }

    rmsnorm_kernel<<<NTOK, 128>>>(x, final_w, out);
}